// round 13
// baseline (speedup 1.0000x reference)
#include <cuda_runtime.h>
#include <cuda_bf16.h>
#include <cstdint>
#include <math.h>

// ---------------------------------------------------------------------------
// Binary CNN fully fused. Round 12: 2 samples per block (dual independent
// dependency chains per thread + amortized weights/barriers).
// Per-sample numerics identical to rounds 5-11 (rel_err == 0.0).
// ---------------------------------------------------------------------------

#define EPSBND 1e-5
#define BAND   1e-3f

__device__ float    g_w1s[32 * 9];
__device__ double   g_inv1d[32], g_bz1d[32];
__device__ double   g_b1d[32];
__device__ float2   g_p1[32];
__device__ __align__(16) unsigned g_wb2[64 * 4];   // sign-folded
__device__ int2     g_kB[64];                 // (K96, K64)
__device__ __align__(16) unsigned g_wb3[128 * 8];  // sign-folded
__device__ int2     g_kC[128];                // (K192, K128)
__device__ unsigned g_wb4t[24 * 128];         // [(h*4+j)*128 + c], sign-folded
__device__ int      g_kD[128];                // K768
__device__ unsigned g_wfb[10 * 64];

__device__ __forceinline__ float bnref(float dv, float bias, float inv, float bz) {
    return __fadd_rn(__fmul_rn(__fadd_rn(dv, bias), inv), bz);
}

__device__ void mk_k(float b, float g, float be, float m, float v,
                     int C0, int C1, int* K0, int* K1)
{
    float inv = __fmul_rn(g, rsqrtf(__fadd_rn(v, 1e-5f)));
    float bz  = __fsub_rn(be, __fmul_rn(m, inv));

    if (inv > 0.0f) {
        int lo = -1025, hi = 1025, ans = 1 << 20;
        while (lo <= hi) {
            int mid = lo + ((hi - lo) >> 1);
            if (bnref((float)mid, b, inv, bz) >= 0.0f) { ans = mid; hi = mid - 1; }
            else lo = mid + 1;
        }
        *K0 = (C0 - ans) >> 1;
        *K1 = (C1 - ans) >> 1;
    } else if (inv < 0.0f) {
        int lo = -1025, hi = 1025, ans = -(1 << 20);
        while (lo <= hi) {
            int mid = lo + ((hi - lo) >> 1);
            if (bnref((float)mid, b, inv, bz) >= 0.0f) { ans = mid; lo = mid + 1; }
            else hi = mid - 1;
        }
        *K0 = (C0 + ans) >> 1;
        *K1 = (C1 + ans) >> 1;
    } else {
        bool always = (bz >= 0.0f);
        *K0 = always ? C0 : -1;
        *K1 = always ? C1 : -1;
    }
}

__global__ void prep_kernel(
    const float* __restrict__ w1, const float* __restrict__ b1,
    const float* __restrict__ w2, const float* __restrict__ b2,
    const float* __restrict__ w3, const float* __restrict__ b3,
    const float* __restrict__ w4, const float* __restrict__ b4,
    const float* __restrict__ g1, const float* __restrict__ be1,
    const float* __restrict__ m1, const float* __restrict__ v1,
    const float* __restrict__ g2, const float* __restrict__ be2,
    const float* __restrict__ m2, const float* __restrict__ v2,
    const float* __restrict__ g3, const float* __restrict__ be3,
    const float* __restrict__ m3, const float* __restrict__ v3,
    const float* __restrict__ g4, const float* __restrict__ be4,
    const float* __restrict__ m4, const float* __restrict__ v4,
    const float* __restrict__ wf)
{
    int u = blockIdx.x * blockDim.x + threadIdx.x;

    if (u < 288) {
        g_w1s[u] = (w1[u] >= 0.f) ? 1.f : -1.f;
        return;
    }
    u -= 288;
    if (u < 32) {
        int c = u;
        double inv = (double)g1[c] / sqrt((double)v1[c] + EPSBND);
        double bz  = (double)be1[c] - (double)m1[c] * inv;
        g_inv1d[c] = inv;
        g_bz1d[c]  = bz;
        g_b1d[c]   = (double)b1[c];
        g_p1[c]    = make_float2((float)inv, (float)((double)b1[c] * inv + bz));
        return;
    }
    u -= 32;
    if (u < 320) {
        if (u < 64) {
            int K0, K1;
            mk_k(b2[u], g2[u], be2[u], m2[u], v2[u], 96, 64, &K0, &K1);
            g_kB[u] = make_int2(K0, K1);
        } else if (u < 192) {
            int c = u - 64, K0, K1;
            mk_k(b3[c], g3[c], be3[c], m3[c], v3[c], 192, 128, &K0, &K1);
            g_kC[c] = make_int2(K0, K1);
        } else {
            int c = u - 192, K0, K1;
            mk_k(b4[c], g4[c], be4[c], m4[c], v4[c], 768, 768, &K0, &K1);
            g_kD[c] = K0;
        }
        return;
    }
    u -= 320;
    if (u < 256) {
        int c = u >> 2, t = u & 3;
        unsigned flip = (g2[c] < 0.f) ? 0xffffffffu : 0u;
        unsigned word = 0;
        if (t < 3) {
            for (int i = 0; i < 32; i++)
                word |= (unsigned)(w2[c * 96 + i * 3 + t] >= 0.f) << i;
            word ^= flip;
        }
        g_wb2[u] = word;
        return;
    }
    u -= 256;
    if (u < 1024) {
        int c = u >> 3, r = u & 7;
        unsigned flip = (g3[c] < 0.f) ? 0xffffffffu : 0u;
        unsigned word = 0;
        if (r < 6) {
            int t = r >> 1, j = r & 1;
            for (int i = 0; i < 32; i++) {
                int cin = j * 32 + i;
                word |= (unsigned)(w3[c * 192 + cin * 3 + t] >= 0.f) << i;
            }
            word ^= flip;
        }
        g_wb3[u] = word;
        return;
    }
    u -= 1024;
    if (u < 3072) {
        int c = u / 24, r = u % 24, h = r >> 2, j = r & 3;
        unsigned flip = (g4[c] < 0.f) ? 0xffffffffu : 0u;
        unsigned word = 0;
        for (int i = 0; i < 32; i++) {
            int cin = j * 32 + i;
            word |= (unsigned)(w4[c * 768 + cin * 6 + h] >= 0.f) << i;
        }
        g_wb4t[(h * 4 + j) * 128 + c] = word ^ flip;
        return;
    }
    u -= 3072;
    if (u < 640) {
        int o = u / 64, jw = u % 64;
        unsigned word = 0;
        for (int i = 0; i < 32; i++)
            word |= (unsigned)(wf[o * 2048 + jw * 32 + i] >= 0.f) << i;
        g_wfb[u] = word;
    }
}

// Rare exact path (double, round-5 chain).
__device__ __noinline__ bool conv1_slow(const float* __restrict__ row, int L)
{
    double inv1 = g_inv1d[L], bz1 = g_bz1d[L], bb1 = g_b1d[L];
    double s0 = 0.0, s1 = 0.0;
#pragma unroll
    for (int t = 0; t < 9; t++) {
        double w = (double)g_w1s[L * 9 + t];
        s0 = fma(w, (double)row[t],     s0);
        s1 = fma(w, (double)row[t + 2], s1);
    }
    double y0 = (s0 + bb1) * inv1 + bz1;
    double y1 = (s1 + bb1) * inv1 + bz1;
    return (y0 >= 0.0) || (y1 >= 0.0);
}

// fp32 fast conv1 pooled-pair (per-sample numerics == rounds 6-11)
__device__ __forceinline__ bool conv1_fast(const float* __restrict__ row,
                                           const float* __restrict__ wrf,
                                           float2 p1, int L)
{
    const float4* rv = (const float4*)row;
    float4 v0 = rv[0], v1 = rv[1], v2 = rv[2];
    float s0, s1;
    s0 = wrf[0] * v0.x;
    s0 = __fmaf_rn(wrf[1], v0.y, s0);
    s0 = __fmaf_rn(wrf[2], v0.z, s0);
    s0 = __fmaf_rn(wrf[3], v0.w, s0);
    s0 = __fmaf_rn(wrf[4], v1.x, s0);
    s0 = __fmaf_rn(wrf[5], v1.y, s0);
    s0 = __fmaf_rn(wrf[6], v1.z, s0);
    s0 = __fmaf_rn(wrf[7], v1.w, s0);
    s0 = __fmaf_rn(wrf[8], v2.x, s0);
    s1 = wrf[0] * v0.z;
    s1 = __fmaf_rn(wrf[1], v0.w, s1);
    s1 = __fmaf_rn(wrf[2], v1.x, s1);
    s1 = __fmaf_rn(wrf[3], v1.y, s1);
    s1 = __fmaf_rn(wrf[4], v1.z, s1);
    s1 = __fmaf_rn(wrf[5], v1.w, s1);
    s1 = __fmaf_rn(wrf[6], v2.x, s1);
    s1 = __fmaf_rn(wrf[7], v2.y, s1);
    s1 = __fmaf_rn(wrf[8], v2.z, s1);
    float ym = fmaxf(__fmaf_rn(s0, p1.x, p1.y), __fmaf_rn(s1, p1.x, p1.y));
    bool bit = (ym >= 0.f);
    if (fabsf(ym) < BAND) bit = conv1_slow(row, L);
    return bit;
}

// ---------------------------------------------------------------------------
// Main fused kernel: 1 block = 2 samples, 128 threads (4 warps).
// ---------------------------------------------------------------------------
__global__ __launch_bounds__(128, 10)
void bcnn_kernel(const float* __restrict__ x, const float* __restrict__ bf,
                 float* __restrict__ out, int B)
{
    const int tid = threadIdx.x;
    const int W   = tid >> 5;
    const int L   = tid & 31;

    const int  b0   = 2 * blockIdx.x;
    const bool has1 = (b0 + 1 < B);
    const int  b1i  = has1 ? (b0 + 1) : b0;

    __shared__ __align__(16) float    xs[2][6 * 136];
    __shared__ __align__(16) unsigned b1s[2][192];
    __shared__ __align__(16) unsigned b2s[2][6 * 68];
    __shared__ __align__(16) unsigned b3s[2][384];
    __shared__ __align__(16) unsigned masks[2][128];

    // load both samples with zero padding
    {
        const float* xb0 = x + (size_t)b0  * 768;
        const float* xb1 = x + (size_t)b1i * 768;
        for (int i = tid; i < 768; i += 128) {
            int r = i >> 7, c = i & 127;
            xs[0][r * 136 + 4 + c] = xb0[i];
            xs[1][r * 136 + 4 + c] = xb1[i];
        }
        if (tid < 96) {
            int ss = tid >= 48, t2 = tid - ss * 48;
            int r = t2 >> 3, j = t2 & 7;
            xs[ss][r * 136 + ((j < 4) ? j : (j + 128))] = 0.f;
        }
    }

    // ---- stage A: conv1 + bias + bn + pool(w2) + binarize, both samples ----
    float wrf[9];
#pragma unroll
    for (int t = 0; t < 9; t++) wrf[t] = g_w1s[L * 9 + t];
    float2 p1 = g_p1[L];
    __syncthreads();

    for (int pos = W; pos < 192; pos += 4) {
        int h = pos >> 5, wp = pos & 31;
        int off = h * 136 + 4 * wp;
        bool bitA = conv1_fast(&xs[0][off], wrf, p1, L);
        bool bitB = conv1_fast(&xs[1][off], wrf, p1, L);
        b1s[0][pos] = __ballot_sync(0xffffffffu, bitA);
        b1s[1][pos] = __ballot_sync(0xffffffffu, bitB);
    }
    __syncthreads();

    // ---- stage B: conv2, quad sliding window, both samples interleaved ----
    {
        int q = W & 1;
        int c = q * 32 + L;
        uint4 wt = *(const uint4*)&g_wb2[c * 4];
        int2 kb = g_kB[c];
        int K96 = kb.x, K64 = kb.y;
        int r0 = 3 * (W >> 1);
        for (int r = r0; r < r0 + 3; r++) {
            const unsigned* rpA = b1s[0] + r * 32;
            const unsigned* rpB = b1s[1] + r * 32;
            unsigned* opA = b2s[0] + r * 68 + 2 + q;
            unsigned* opB = b2s[1] + r * 68 + 2 + q;
            uint4 A = *(const uint4*)rpA;
            uint4 Bv = *(const uint4*)rpB;
            {
                int sA = __popc(A.x ^ wt.y) + __popc(A.y ^ wt.z);
                int sB = __popc(Bv.x ^ wt.y) + __popc(Bv.y ^ wt.z);
                opA[0] = __ballot_sync(0xffffffffu, sA <= K64);
                opB[0] = __ballot_sync(0xffffffffu, sB <= K64);
            }
            {
                int sA = __popc(A.x ^ wt.x) + __popc(A.y ^ wt.y) + __popc(A.z ^ wt.z);
                int sB = __popc(Bv.x ^ wt.x) + __popc(Bv.y ^ wt.y) + __popc(Bv.z ^ wt.z);
                opA[2] = __ballot_sync(0xffffffffu, sA <= K96);
                opB[2] = __ballot_sync(0xffffffffu, sB <= K96);
            }
            {
                int sA = __popc(A.y ^ wt.x) + __popc(A.z ^ wt.y) + __popc(A.w ^ wt.z);
                int sB = __popc(Bv.y ^ wt.x) + __popc(Bv.z ^ wt.y) + __popc(Bv.w ^ wt.z);
                opA[4] = __ballot_sync(0xffffffffu, sA <= K96);
                opB[4] = __ballot_sync(0xffffffffu, sB <= K96);
            }
            unsigned pA2 = A.z, pA3 = A.w, pB2 = Bv.z, pB3 = Bv.w;
#pragma unroll
            for (int k = 1; k < 8; k++) {
                A  = *(const uint4*)(rpA + 4 * k);
                Bv = *(const uint4*)(rpB + 4 * k);
                int sA, sB;
                sA = __popc(pA2 ^ wt.x) + __popc(pA3 ^ wt.y) + __popc(A.x ^ wt.z);
                sB = __popc(pB2 ^ wt.x) + __popc(pB3 ^ wt.y) + __popc(Bv.x ^ wt.z);
                opA[2 * (4 * k - 1)] = __ballot_sync(0xffffffffu, sA <= K96);
                opB[2 * (4 * k - 1)] = __ballot_sync(0xffffffffu, sB <= K96);
                sA = __popc(pA3 ^ wt.x) + __popc(A.x ^ wt.y) + __popc(A.y ^ wt.z);
                sB = __popc(pB3 ^ wt.x) + __popc(Bv.x ^ wt.y) + __popc(Bv.y ^ wt.z);
                opA[2 * (4 * k)] = __ballot_sync(0xffffffffu, sA <= K96);
                opB[2 * (4 * k)] = __ballot_sync(0xffffffffu, sB <= K96);
                sA = __popc(A.x ^ wt.x) + __popc(A.y ^ wt.y) + __popc(A.z ^ wt.z);
                sB = __popc(Bv.x ^ wt.x) + __popc(Bv.y ^ wt.y) + __popc(Bv.z ^ wt.z);
                opA[2 * (4 * k + 1)] = __ballot_sync(0xffffffffu, sA <= K96);
                opB[2 * (4 * k + 1)] = __ballot_sync(0xffffffffu, sB <= K96);
                sA = __popc(A.y ^ wt.x) + __popc(A.z ^ wt.y) + __popc(A.w ^ wt.z);
                sB = __popc(Bv.y ^ wt.x) + __popc(Bv.z ^ wt.y) + __popc(Bv.w ^ wt.z);
                opA[2 * (4 * k + 2)] = __ballot_sync(0xffffffffu, sA <= K96);
                opB[2 * (4 * k + 2)] = __ballot_sync(0xffffffffu, sB <= K96);
                pA2 = A.z; pA3 = A.w; pB2 = Bv.z; pB3 = Bv.w;
            }
            {
                int sA = __popc(pA2 ^ wt.x) + __popc(pA3 ^ wt.y);
                int sB = __popc(pB2 ^ wt.x) + __popc(pB3 ^ wt.y);
                opA[62] = __ballot_sync(0xffffffffu, sA <= K64);
                opB[62] = __ballot_sync(0xffffffffu, sB <= K64);
            }
        }
    }
    __syncthreads();

    // ---- stage C: conv3 + pool(w2); 12 (sample,h) rows, sliding window ----
    {
        int c = tid;
        uint4 wAB = *(const uint4*)&g_wb3[c * 8];
        uint2 wC  = *(const uint2*)&g_wb3[c * 8 + 4];
        int2 kc = g_kC[c];
        int K192 = kc.x, K128 = kc.y;

        for (int t = 0; t < 12; t++) {
            int samp = t & 1, h = t >> 1;
            const unsigned* rp2 = b2s[samp] + h * 68 + 2;
            unsigned* ob = b3s[samp] + h * 64;
            unsigned Wd[12];
            {
                uint2 a = *(const uint2*)(rp2 + 0);
                uint4 bq = *(const uint4*)(rp2 + 2);
                Wd[2] = a.x;  Wd[3] = a.y;
                Wd[4] = bq.x; Wd[5] = bq.y; Wd[6] = bq.z; Wd[7] = bq.w;
            }
            {
                uint4 p = *(const uint4*)(rp2 + 6);
                Wd[8] = p.x; Wd[9] = p.y; Wd[10] = p.z; Wd[11] = p.w;
            }
            {   // wp = 0
                int s0 = __popc(Wd[2] ^ wAB.z) + __popc(Wd[3] ^ wAB.w)
                       + __popc(Wd[4] ^ wC.x)  + __popc(Wd[5] ^ wC.y);
                int s1 = __popc(Wd[2] ^ wAB.x) + __popc(Wd[3] ^ wAB.y)
                       + __popc(Wd[4] ^ wAB.z) + __popc(Wd[5] ^ wAB.w)
                       + __popc(Wd[6] ^ wC.x)  + __popc(Wd[7] ^ wC.y);
                bool bit = (s0 <= K128) || (s1 <= K192);
                ob[W] = __ballot_sync(0xffffffffu, bit);
            }
#pragma unroll
            for (int i = 0; i < 8; i++) Wd[i] = Wd[i + 4];

#pragma unroll
            for (int wp = 1; wp < 15; wp++) {
                uint4 p = *(const uint4*)(rp2 + 4 * wp + 6);
                Wd[8] = p.x; Wd[9] = p.y; Wd[10] = p.z; Wd[11] = p.w;
                int s0 = __popc(Wd[0] ^ wAB.x) + __popc(Wd[1] ^ wAB.y)
                       + __popc(Wd[2] ^ wAB.z) + __popc(Wd[3] ^ wAB.w)
                       + __popc(Wd[4] ^ wC.x)  + __popc(Wd[5] ^ wC.y);
                int s1 = __popc(Wd[2] ^ wAB.x) + __popc(Wd[3] ^ wAB.y)
                       + __popc(Wd[4] ^ wAB.z) + __popc(Wd[5] ^ wAB.w)
                       + __popc(Wd[6] ^ wC.x)  + __popc(Wd[7] ^ wC.y);
                bool bit = (s0 <= K192) || (s1 <= K192);
                ob[wp * 4 + W] = __ballot_sync(0xffffffffu, bit);
#pragma unroll
                for (int i = 0; i < 8; i++) Wd[i] = Wd[i + 4];
            }
            {   // wp = 15
                int s0 = __popc(Wd[0] ^ wAB.x) + __popc(Wd[1] ^ wAB.y)
                       + __popc(Wd[2] ^ wAB.z) + __popc(Wd[3] ^ wAB.w)
                       + __popc(Wd[4] ^ wC.x)  + __popc(Wd[5] ^ wC.y);
                int s1 = __popc(Wd[2] ^ wAB.x) + __popc(Wd[3] ^ wAB.y)
                       + __popc(Wd[4] ^ wAB.z) + __popc(Wd[5] ^ wAB.w);
                bool bit = (s0 <= K192) || (s1 <= K128);
                ob[60 + W] = __ballot_sync(0xffffffffu, bit);
            }
        }
    }
    __syncthreads();

    // ---- stage D: conv4, both samples, shared transposed weights ----
    {
        int c = tid;
        int K = g_kD[c];
        unsigned maskA = 0, maskB = 0;
#pragma unroll
        for (int pass = 0; pass < 2; pass++) {
            int sA[8], sB[8];
#pragma unroll
            for (int w = 0; w < 8; w++) { sA[w] = 0; sB[w] = 0; }
#pragma unroll
            for (int h = 0; h < 6; h++) {
                const unsigned* wp4 = g_wb4t + (h * 4) * 128 + c;
                unsigned w0 = wp4[0], w1 = wp4[128], w2 = wp4[256], w3 = wp4[384];
#pragma unroll
                for (int w = 0; w < 8; w++) {
                    int idx = (h * 16 + pass * 8 + w) * 4;
                    uint4 A  = *(const uint4*)&b3s[0][idx];
                    uint4 Bv = *(const uint4*)&b3s[1][idx];
                    sA[w] += __popc(A.x ^ w0) + __popc(A.y ^ w1)
                           + __popc(A.z ^ w2) + __popc(A.w ^ w3);
                    sB[w] += __popc(Bv.x ^ w0) + __popc(Bv.y ^ w1)
                           + __popc(Bv.z ^ w2) + __popc(Bv.w ^ w3);
                }
            }
#pragma unroll
            for (int w = 0; w < 8; w++) {
                maskA |= (sA[w] <= K) ? (1u << (pass * 8 + w)) : 0u;
                maskB |= (sB[w] <= K) ? (1u << (pass * 8 + w)) : 0u;
            }
        }
        masks[0][c] = maskA;
        masks[1][c] = maskB;
    }
    __syncthreads();

    // ---- stage E: fused repack + fc, both samples ----
    {
        uint2 a0 = *(const uint2*)&masks[0][2 * L];
        uint2 a1 = *(const uint2*)&masks[0][64 + 2 * L];
        uint2 c0 = *(const uint2*)&masks[1][2 * L];
        uint2 c1 = *(const uint2*)&masks[1][64 + 2 * L];
        unsigned fA0 = a0.x | (a0.y << 16);
        unsigned fA1 = a1.x | (a1.y << 16);
        unsigned fB0 = c0.x | (c0.y << 16);
        unsigned fB1 = c1.x | (c1.y << 16);
        for (int o = W; o < 10; o += 4) {
            unsigned wf0 = g_wfb[o * 64 + L], wf1 = g_wfb[o * 64 + 32 + L];
            int sA = __popc(fA0 ^ wf0) + __popc(fA1 ^ wf1);
            int sB = __popc(fB0 ^ wf0) + __popc(fB1 ^ wf1);
            int totA = __reduce_add_sync(0xffffffffu, sA);
            int totB = __reduce_add_sync(0xffffffffu, sB);
            if (L == 0) {
                out[(size_t)b0 * 10 + o] = (float)(2048 - 2 * totA) + bf[o];
                if (has1)
                    out[(size_t)(b0 + 1) * 10 + o] = (float)(2048 - 2 * totB) + bf[o];
            }
        }
    }
}

extern "C" void kernel_launch(void* const* d_in, const int* in_sizes, int n_in,
                              void* d_out, int out_size)
{
    const float* x   = (const float*)d_in[0];
    const float* w1  = (const float*)d_in[1];
    const float* b1  = (const float*)d_in[2];
    const float* w2  = (const float*)d_in[3];
    const float* b2  = (const float*)d_in[4];
    const float* w3  = (const float*)d_in[5];
    const float* b3  = (const float*)d_in[6];
    const float* w4  = (const float*)d_in[7];
    const float* b4  = (const float*)d_in[8];
    const float* g1  = (const float*)d_in[9];
    const float* be1 = (const float*)d_in[10];
    const float* m1  = (const float*)d_in[11];
    const float* v1  = (const float*)d_in[12];
    const float* g2  = (const float*)d_in[13];
    const float* be2 = (const float*)d_in[14];
    const float* m2  = (const float*)d_in[15];
    const float* v2  = (const float*)d_in[16];
    const float* g3  = (const float*)d_in[17];
    const float* be3 = (const float*)d_in[18];
    const float* m3  = (const float*)d_in[19];
    const float* v3  = (const float*)d_in[20];
    const float* g4  = (const float*)d_in[21];
    const float* be4 = (const float*)d_in[22];
    const float* m4  = (const float*)d_in[23];
    const float* v4  = (const float*)d_in[24];
    const float* wf  = (const float*)d_in[25];
    const float* bf  = (const float*)d_in[26];

    int B = in_sizes[0] / 768;

    prep_kernel<<<22, 256>>>(w1, b1, w2, b2, w3, b3, w4, b4,
                             g1, be1, m1, v1, g2, be2, m2, v2,
                             g3, be3, m3, v3, g4, be4, m4, v4, wf);
    bcnn_kernel<<<(B + 1) / 2, 128>>>(x, bf, (float*)d_out, B);
}

// round 14
// speedup vs baseline: 1.0051x; 1.0051x over previous
#include <cuda_runtime.h>
#include <cuda_bf16.h>
#include <cstdint>
#include <math.h>

// ---------------------------------------------------------------------------
// Binary CNN fully fused. Round 14: intra-warp software pipelining.
//  - stage C: 2 independent row-windows in flight (h, h+1) per warp
//  - stage B: all 3 rows of a warp interleaved (3 chains)
//  - 1 sample/block (grid 8192, minimal wave tail), no forced block cap
// Per-sample numerics identical to rounds 5-12 (rel_err == 0.0).
// ---------------------------------------------------------------------------

#define EPSBND 1e-5
#define BAND   1e-3f

__device__ float    g_w1s[32 * 9];
__device__ double   g_inv1d[32], g_bz1d[32];
__device__ double   g_b1d[32];
__device__ float2   g_p1[32];
__device__ __align__(16) unsigned g_wb2[64 * 4];   // sign-folded
__device__ int2     g_kB[64];                 // (K96, K64)
__device__ __align__(16) unsigned g_wb3[128 * 8];  // sign-folded
__device__ int2     g_kC[128];                // (K192, K128)
__device__ unsigned g_wb4t[24 * 128];         // [(h*4+j)*128 + c], sign-folded
__device__ int      g_kD[128];                // K768
__device__ unsigned g_wfb[10 * 64];

__device__ __forceinline__ float bnref(float dv, float bias, float inv, float bz) {
    return __fadd_rn(__fmul_rn(__fadd_rn(dv, bias), inv), bz);
}

__device__ void mk_k(float b, float g, float be, float m, float v,
                     int C0, int C1, int* K0, int* K1)
{
    float inv = __fmul_rn(g, rsqrtf(__fadd_rn(v, 1e-5f)));
    float bz  = __fsub_rn(be, __fmul_rn(m, inv));

    if (inv > 0.0f) {
        int lo = -1025, hi = 1025, ans = 1 << 20;
        while (lo <= hi) {
            int mid = lo + ((hi - lo) >> 1);
            if (bnref((float)mid, b, inv, bz) >= 0.0f) { ans = mid; hi = mid - 1; }
            else lo = mid + 1;
        }
        *K0 = (C0 - ans) >> 1;
        *K1 = (C1 - ans) >> 1;
    } else if (inv < 0.0f) {
        int lo = -1025, hi = 1025, ans = -(1 << 20);
        while (lo <= hi) {
            int mid = lo + ((hi - lo) >> 1);
            if (bnref((float)mid, b, inv, bz) >= 0.0f) { ans = mid; lo = mid + 1; }
            else hi = mid - 1;
        }
        *K0 = (C0 + ans) >> 1;
        *K1 = (C1 + ans) >> 1;
    } else {
        bool always = (bz >= 0.0f);
        *K0 = always ? C0 : -1;
        *K1 = always ? C1 : -1;
    }
}

__global__ void prep_kernel(
    const float* __restrict__ w1, const float* __restrict__ b1,
    const float* __restrict__ w2, const float* __restrict__ b2,
    const float* __restrict__ w3, const float* __restrict__ b3,
    const float* __restrict__ w4, const float* __restrict__ b4,
    const float* __restrict__ g1, const float* __restrict__ be1,
    const float* __restrict__ m1, const float* __restrict__ v1,
    const float* __restrict__ g2, const float* __restrict__ be2,
    const float* __restrict__ m2, const float* __restrict__ v2,
    const float* __restrict__ g3, const float* __restrict__ be3,
    const float* __restrict__ m3, const float* __restrict__ v3,
    const float* __restrict__ g4, const float* __restrict__ be4,
    const float* __restrict__ m4, const float* __restrict__ v4,
    const float* __restrict__ wf)
{
    int u = blockIdx.x * blockDim.x + threadIdx.x;

    if (u < 288) {
        g_w1s[u] = (w1[u] >= 0.f) ? 1.f : -1.f;
        return;
    }
    u -= 288;
    if (u < 32) {
        int c = u;
        double inv = (double)g1[c] / sqrt((double)v1[c] + EPSBND);
        double bz  = (double)be1[c] - (double)m1[c] * inv;
        g_inv1d[c] = inv;
        g_bz1d[c]  = bz;
        g_b1d[c]   = (double)b1[c];
        g_p1[c]    = make_float2((float)inv, (float)((double)b1[c] * inv + bz));
        return;
    }
    u -= 32;
    if (u < 320) {
        if (u < 64) {
            int K0, K1;
            mk_k(b2[u], g2[u], be2[u], m2[u], v2[u], 96, 64, &K0, &K1);
            g_kB[u] = make_int2(K0, K1);
        } else if (u < 192) {
            int c = u - 64, K0, K1;
            mk_k(b3[c], g3[c], be3[c], m3[c], v3[c], 192, 128, &K0, &K1);
            g_kC[c] = make_int2(K0, K1);
        } else {
            int c = u - 192, K0, K1;
            mk_k(b4[c], g4[c], be4[c], m4[c], v4[c], 768, 768, &K0, &K1);
            g_kD[c] = K0;
        }
        return;
    }
    u -= 320;
    if (u < 256) {
        int c = u >> 2, t = u & 3;
        unsigned flip = (g2[c] < 0.f) ? 0xffffffffu : 0u;
        unsigned word = 0;
        if (t < 3) {
            for (int i = 0; i < 32; i++)
                word |= (unsigned)(w2[c * 96 + i * 3 + t] >= 0.f) << i;
            word ^= flip;
        }
        g_wb2[u] = word;
        return;
    }
    u -= 256;
    if (u < 1024) {
        int c = u >> 3, r = u & 7;
        unsigned flip = (g3[c] < 0.f) ? 0xffffffffu : 0u;
        unsigned word = 0;
        if (r < 6) {
            int t = r >> 1, j = r & 1;
            for (int i = 0; i < 32; i++) {
                int cin = j * 32 + i;
                word |= (unsigned)(w3[c * 192 + cin * 3 + t] >= 0.f) << i;
            }
            word ^= flip;
        }
        g_wb3[u] = word;
        return;
    }
    u -= 1024;
    if (u < 3072) {
        int c = u / 24, r = u % 24, h = r >> 2, j = r & 3;
        unsigned flip = (g4[c] < 0.f) ? 0xffffffffu : 0u;
        unsigned word = 0;
        for (int i = 0; i < 32; i++) {
            int cin = j * 32 + i;
            word |= (unsigned)(w4[c * 768 + cin * 6 + h] >= 0.f) << i;
        }
        g_wb4t[(h * 4 + j) * 128 + c] = word ^ flip;
        return;
    }
    u -= 3072;
    if (u < 640) {
        int o = u / 64, jw = u % 64;
        unsigned word = 0;
        for (int i = 0; i < 32; i++)
            word |= (unsigned)(wf[o * 2048 + jw * 32 + i] >= 0.f) << i;
        g_wfb[u] = word;
    }
}

// Rare exact path (double, round-5 chain).
__device__ __noinline__ bool conv1_slow(const float* __restrict__ row, int L)
{
    double inv1 = g_inv1d[L], bz1 = g_bz1d[L], bb1 = g_b1d[L];
    double s0 = 0.0, s1 = 0.0;
#pragma unroll
    for (int t = 0; t < 9; t++) {
        double w = (double)g_w1s[L * 9 + t];
        s0 = fma(w, (double)row[t],     s0);
        s1 = fma(w, (double)row[t + 2], s1);
    }
    double y0 = (s0 + bb1) * inv1 + bz1;
    double y1 = (s1 + bb1) * inv1 + bz1;
    return (y0 >= 0.0) || (y1 >= 0.0);
}

// ---------------------------------------------------------------------------
// Main fused kernel: 1 block = 1 sample, 128 threads (4 warps).
// ---------------------------------------------------------------------------
__global__ __launch_bounds__(128)
void bcnn_kernel(const float* __restrict__ x, const float* __restrict__ bf,
                 float* __restrict__ out)
{
    const int b   = blockIdx.x;
    const int tid = threadIdx.x;
    const int W   = tid >> 5;
    const int L   = tid & 31;

    __shared__ __align__(16) float    xs[6 * 136];
    __shared__ __align__(16) unsigned b1s[192];
    __shared__ __align__(16) unsigned b2s[6 * 68];   // row r word k at [r*68+2+k]
    __shared__ __align__(16) unsigned b3s[384];
    __shared__ __align__(16) unsigned masks[128];

    // load sample with zero padding (4 cols each side)
    const float* xb = x + (size_t)b * 768;
    for (int i = tid; i < 768; i += 128) {
        int r = i >> 7, c = i & 127;
        xs[r * 136 + 4 + c] = xb[i];
    }
    if (tid < 48) {
        int r = tid >> 3, j = tid & 7;
        xs[r * 136 + ((j < 4) ? j : (j + 128))] = 0.f;
    }

    // ---- stage A: conv1 + bias + bn + pool(w2) + binarize ----
    float wrf[9];
#pragma unroll
    for (int t = 0; t < 9; t++) wrf[t] = g_w1s[L * 9 + t];
    float2 p1 = g_p1[L];
    __syncthreads();

    for (int pos = W; pos < 192; pos += 4) {
        int h = pos >> 5, wp = pos & 31;
        const float* row = xs + h * 136 + 4 * wp;
        const float4* rv = (const float4*)row;
        float4 v0 = rv[0], v1 = rv[1], v2 = rv[2];
        float s0, s1;
        s0 = wrf[0] * v0.x;
        s0 = __fmaf_rn(wrf[1], v0.y, s0);
        s0 = __fmaf_rn(wrf[2], v0.z, s0);
        s0 = __fmaf_rn(wrf[3], v0.w, s0);
        s0 = __fmaf_rn(wrf[4], v1.x, s0);
        s0 = __fmaf_rn(wrf[5], v1.y, s0);
        s0 = __fmaf_rn(wrf[6], v1.z, s0);
        s0 = __fmaf_rn(wrf[7], v1.w, s0);
        s0 = __fmaf_rn(wrf[8], v2.x, s0);
        s1 = wrf[0] * v0.z;
        s1 = __fmaf_rn(wrf[1], v0.w, s1);
        s1 = __fmaf_rn(wrf[2], v1.x, s1);
        s1 = __fmaf_rn(wrf[3], v1.y, s1);
        s1 = __fmaf_rn(wrf[4], v1.z, s1);
        s1 = __fmaf_rn(wrf[5], v1.w, s1);
        s1 = __fmaf_rn(wrf[6], v2.x, s1);
        s1 = __fmaf_rn(wrf[7], v2.y, s1);
        s1 = __fmaf_rn(wrf[8], v2.z, s1);
        float ym = fmaxf(__fmaf_rn(s0, p1.x, p1.y), __fmaf_rn(s1, p1.x, p1.y));
        bool bit = (ym >= 0.f);
        if (fabsf(ym) < BAND) bit = conv1_slow(row, L);
        b1s[pos] = __ballot_sync(0xffffffffu, bit);
    }
    __syncthreads();

    // ---- stage B: conv2, 3 rows interleaved (3 independent chains) ----
    {
        int q = W & 1;
        int c = q * 32 + L;
        uint4 wt = *(const uint4*)&g_wb2[c * 4];
        int2 kb = g_kB[c];
        int K96 = kb.x, K64 = kb.y;
        int r0 = 3 * (W >> 1);
        const unsigned* rp0 = b1s + r0 * 32;
        const unsigned* rp1 = rp0 + 32;
        const unsigned* rp2 = rp0 + 64;
        unsigned* o0 = b2s + r0 * 68 + 2 + q;
        unsigned* o1 = o0 + 68;
        unsigned* o2 = o0 + 136;

        uint4 A0 = *(const uint4*)rp0;
        uint4 A1 = *(const uint4*)rp1;
        uint4 A2 = *(const uint4*)rp2;
        {   // w = 0
            int s0 = __popc(A0.x ^ wt.y) + __popc(A0.y ^ wt.z);
            int s1 = __popc(A1.x ^ wt.y) + __popc(A1.y ^ wt.z);
            int s2 = __popc(A2.x ^ wt.y) + __popc(A2.y ^ wt.z);
            o0[0] = __ballot_sync(0xffffffffu, s0 <= K64);
            o1[0] = __ballot_sync(0xffffffffu, s1 <= K64);
            o2[0] = __ballot_sync(0xffffffffu, s2 <= K64);
        }
        {   // w = 1
            int s0 = __popc(A0.x ^ wt.x) + __popc(A0.y ^ wt.y) + __popc(A0.z ^ wt.z);
            int s1 = __popc(A1.x ^ wt.x) + __popc(A1.y ^ wt.y) + __popc(A1.z ^ wt.z);
            int s2 = __popc(A2.x ^ wt.x) + __popc(A2.y ^ wt.y) + __popc(A2.z ^ wt.z);
            o0[2] = __ballot_sync(0xffffffffu, s0 <= K96);
            o1[2] = __ballot_sync(0xffffffffu, s1 <= K96);
            o2[2] = __ballot_sync(0xffffffffu, s2 <= K96);
        }
        {   // w = 2
            int s0 = __popc(A0.y ^ wt.x) + __popc(A0.z ^ wt.y) + __popc(A0.w ^ wt.z);
            int s1 = __popc(A1.y ^ wt.x) + __popc(A1.z ^ wt.y) + __popc(A1.w ^ wt.z);
            int s2 = __popc(A2.y ^ wt.x) + __popc(A2.z ^ wt.y) + __popc(A2.w ^ wt.z);
            o0[4] = __ballot_sync(0xffffffffu, s0 <= K96);
            o1[4] = __ballot_sync(0xffffffffu, s1 <= K96);
            o2[4] = __ballot_sync(0xffffffffu, s2 <= K96);
        }
        unsigned p02 = A0.z, p03 = A0.w;
        unsigned p12 = A1.z, p13 = A1.w;
        unsigned p22 = A2.z, p23 = A2.w;
#pragma unroll
        for (int k = 1; k < 8; k++) {
            A0 = *(const uint4*)(rp0 + 4 * k);
            A1 = *(const uint4*)(rp1 + 4 * k);
            A2 = *(const uint4*)(rp2 + 4 * k);
            int s0, s1, s2;
            s0 = __popc(p02 ^ wt.x) + __popc(p03 ^ wt.y) + __popc(A0.x ^ wt.z);
            s1 = __popc(p12 ^ wt.x) + __popc(p13 ^ wt.y) + __popc(A1.x ^ wt.z);
            s2 = __popc(p22 ^ wt.x) + __popc(p23 ^ wt.y) + __popc(A2.x ^ wt.z);
            o0[2 * (4 * k - 1)] = __ballot_sync(0xffffffffu, s0 <= K96);
            o1[2 * (4 * k - 1)] = __ballot_sync(0xffffffffu, s1 <= K96);
            o2[2 * (4 * k - 1)] = __ballot_sync(0xffffffffu, s2 <= K96);
            s0 = __popc(p03 ^ wt.x) + __popc(A0.x ^ wt.y) + __popc(A0.y ^ wt.z);
            s1 = __popc(p13 ^ wt.x) + __popc(A1.x ^ wt.y) + __popc(A1.y ^ wt.z);
            s2 = __popc(p23 ^ wt.x) + __popc(A2.x ^ wt.y) + __popc(A2.y ^ wt.z);
            o0[2 * (4 * k)] = __ballot_sync(0xffffffffu, s0 <= K96);
            o1[2 * (4 * k)] = __ballot_sync(0xffffffffu, s1 <= K96);
            o2[2 * (4 * k)] = __ballot_sync(0xffffffffu, s2 <= K96);
            s0 = __popc(A0.x ^ wt.x) + __popc(A0.y ^ wt.y) + __popc(A0.z ^ wt.z);
            s1 = __popc(A1.x ^ wt.x) + __popc(A1.y ^ wt.y) + __popc(A1.z ^ wt.z);
            s2 = __popc(A2.x ^ wt.x) + __popc(A2.y ^ wt.y) + __popc(A2.z ^ wt.z);
            o0[2 * (4 * k + 1)] = __ballot_sync(0xffffffffu, s0 <= K96);
            o1[2 * (4 * k + 1)] = __ballot_sync(0xffffffffu, s1 <= K96);
            o2[2 * (4 * k + 1)] = __ballot_sync(0xffffffffu, s2 <= K96);
            s0 = __popc(A0.y ^ wt.x) + __popc(A0.z ^ wt.y) + __popc(A0.w ^ wt.z);
            s1 = __popc(A1.y ^ wt.x) + __popc(A1.z ^ wt.y) + __popc(A1.w ^ wt.z);
            s2 = __popc(A2.y ^ wt.x) + __popc(A2.z ^ wt.y) + __popc(A2.w ^ wt.z);
            o0[2 * (4 * k + 2)] = __ballot_sync(0xffffffffu, s0 <= K96);
            o1[2 * (4 * k + 2)] = __ballot_sync(0xffffffffu, s1 <= K96);
            o2[2 * (4 * k + 2)] = __ballot_sync(0xffffffffu, s2 <= K96);
            p02 = A0.z; p03 = A0.w;
            p12 = A1.z; p13 = A1.w;
            p22 = A2.z; p23 = A2.w;
        }
        {   // w = 31
            int s0 = __popc(p02 ^ wt.x) + __popc(p03 ^ wt.y);
            int s1 = __popc(p12 ^ wt.x) + __popc(p13 ^ wt.y);
            int s2 = __popc(p22 ^ wt.x) + __popc(p23 ^ wt.y);
            o0[62] = __ballot_sync(0xffffffffu, s0 <= K64);
            o1[62] = __ballot_sync(0xffffffffu, s1 <= K64);
            o2[62] = __ballot_sync(0xffffffffu, s2 <= K64);
        }
    }
    __syncthreads();

    // ---- stage C: conv3 + pool(w2); 2 row-windows in flight ----
    {
        int c = tid;
        uint4 wAB = *(const uint4*)&g_wb3[c * 8];      // w00 w01 w10 w11
        uint2 wC  = *(const uint2*)&g_wb3[c * 8 + 4];  // w20 w21
        int2 kc = g_kC[c];
        int K192 = kc.x, K128 = kc.y;

        for (int hp = 0; hp < 3; hp++) {
            const unsigned* rpA = b2s + (2 * hp) * 68 + 2;
            const unsigned* rpB = rpA + 68;
            unsigned* obA = b3s + (2 * hp) * 64;
            unsigned* obB = obA + 64;
            unsigned WA[12], WB[12];
            {
                uint2 aA = *(const uint2*)(rpA + 0);
                uint2 aB = *(const uint2*)(rpB + 0);
                uint4 bA = *(const uint4*)(rpA + 2);
                uint4 bB = *(const uint4*)(rpB + 2);
                WA[2] = aA.x; WA[3] = aA.y;
                WB[2] = aB.x; WB[3] = aB.y;
                WA[4] = bA.x; WA[5] = bA.y; WA[6] = bA.z; WA[7] = bA.w;
                WB[4] = bB.x; WB[5] = bB.y; WB[6] = bB.z; WB[7] = bB.w;
            }
            {
                uint4 pA = *(const uint4*)(rpA + 6);
                uint4 pB = *(const uint4*)(rpB + 6);
                WA[8] = pA.x; WA[9] = pA.y; WA[10] = pA.z; WA[11] = pA.w;
                WB[8] = pB.x; WB[9] = pB.y; WB[10] = pB.z; WB[11] = pB.w;
            }
            {   // wp = 0
                int sA0 = __popc(WA[2] ^ wAB.z) + __popc(WA[3] ^ wAB.w)
                        + __popc(WA[4] ^ wC.x)  + __popc(WA[5] ^ wC.y);
                int sB0 = __popc(WB[2] ^ wAB.z) + __popc(WB[3] ^ wAB.w)
                        + __popc(WB[4] ^ wC.x)  + __popc(WB[5] ^ wC.y);
                int sA1 = __popc(WA[2] ^ wAB.x) + __popc(WA[3] ^ wAB.y)
                        + __popc(WA[4] ^ wAB.z) + __popc(WA[5] ^ wAB.w)
                        + __popc(WA[6] ^ wC.x)  + __popc(WA[7] ^ wC.y);
                int sB1 = __popc(WB[2] ^ wAB.x) + __popc(WB[3] ^ wAB.y)
                        + __popc(WB[4] ^ wAB.z) + __popc(WB[5] ^ wAB.w)
                        + __popc(WB[6] ^ wC.x)  + __popc(WB[7] ^ wC.y);
                bool bA = (sA0 <= K128) || (sA1 <= K192);
                bool bB = (sB0 <= K128) || (sB1 <= K192);
                obA[W] = __ballot_sync(0xffffffffu, bA);
                obB[W] = __ballot_sync(0xffffffffu, bB);
            }
#pragma unroll
            for (int i = 0; i < 8; i++) { WA[i] = WA[i + 4]; WB[i] = WB[i + 4]; }

#pragma unroll
            for (int wp = 1; wp < 15; wp++) {
                uint4 pA = *(const uint4*)(rpA + 4 * wp + 6);
                uint4 pB = *(const uint4*)(rpB + 4 * wp + 6);
                WA[8] = pA.x; WA[9] = pA.y; WA[10] = pA.z; WA[11] = pA.w;
                WB[8] = pB.x; WB[9] = pB.y; WB[10] = pB.z; WB[11] = pB.w;
                int sA0 = __popc(WA[0] ^ wAB.x) + __popc(WA[1] ^ wAB.y)
                        + __popc(WA[2] ^ wAB.z) + __popc(WA[3] ^ wAB.w)
                        + __popc(WA[4] ^ wC.x)  + __popc(WA[5] ^ wC.y);
                int sB0 = __popc(WB[0] ^ wAB.x) + __popc(WB[1] ^ wAB.y)
                        + __popc(WB[2] ^ wAB.z) + __popc(WB[3] ^ wAB.w)
                        + __popc(WB[4] ^ wC.x)  + __popc(WB[5] ^ wC.y);
                int sA1 = __popc(WA[2] ^ wAB.x) + __popc(WA[3] ^ wAB.y)
                        + __popc(WA[4] ^ wAB.z) + __popc(WA[5] ^ wAB.w)
                        + __popc(WA[6] ^ wC.x)  + __popc(WA[7] ^ wC.y);
                int sB1 = __popc(WB[2] ^ wAB.x) + __popc(WB[3] ^ wAB.y)
                        + __popc(WB[4] ^ wAB.z) + __popc(WB[5] ^ wAB.w)
                        + __popc(WB[6] ^ wC.x)  + __popc(WB[7] ^ wC.y);
                bool bA = (sA0 <= K192) || (sA1 <= K192);
                bool bB = (sB0 <= K192) || (sB1 <= K192);
                obA[wp * 4 + W] = __ballot_sync(0xffffffffu, bA);
                obB[wp * 4 + W] = __ballot_sync(0xffffffffu, bB);
#pragma unroll
                for (int i = 0; i < 8; i++) { WA[i] = WA[i + 4]; WB[i] = WB[i + 4]; }
            }
            {   // wp = 15
                int sA0 = __popc(WA[0] ^ wAB.x) + __popc(WA[1] ^ wAB.y)
                        + __popc(WA[2] ^ wAB.z) + __popc(WA[3] ^ wAB.w)
                        + __popc(WA[4] ^ wC.x)  + __popc(WA[5] ^ wC.y);
                int sB0 = __popc(WB[0] ^ wAB.x) + __popc(WB[1] ^ wAB.y)
                        + __popc(WB[2] ^ wAB.z) + __popc(WB[3] ^ wAB.w)
                        + __popc(WB[4] ^ wC.x)  + __popc(WB[5] ^ wC.y);
                int sA1 = __popc(WA[2] ^ wAB.x) + __popc(WA[3] ^ wAB.y)
                        + __popc(WA[4] ^ wAB.z) + __popc(WA[5] ^ wAB.w);
                int sB1 = __popc(WB[2] ^ wAB.x) + __popc(WB[3] ^ wAB.y)
                        + __popc(WB[4] ^ wAB.z) + __popc(WB[5] ^ wAB.w);
                bool bA = (sA0 <= K192) || (sA1 <= K128);
                bool bB = (sB0 <= K192) || (sB1 <= K128);
                obA[60 + W] = __ballot_sync(0xffffffffu, bA);
                obB[60 + W] = __ballot_sync(0xffffffffu, bB);
            }
        }
    }
    __syncthreads();

    // ---- stage D: conv4, coalesced transposed weights, 16 accumulators ----
    {
        int c = tid;
        int s[16];
#pragma unroll
        for (int w = 0; w < 16; w++) s[w] = 0;
#pragma unroll
        for (int h = 0; h < 6; h++) {
            const unsigned* wp4 = g_wb4t + (h * 4) * 128 + c;
            unsigned w0 = wp4[0], w1 = wp4[128], w2 = wp4[256], w3 = wp4[384];
#pragma unroll
            for (int w = 0; w < 16; w++) {
                uint4 A = *(const uint4*)&b3s[(h * 16 + w) * 4];
                s[w] += __popc(A.x ^ w0) + __popc(A.y ^ w1)
                      + __popc(A.z ^ w2) + __popc(A.w ^ w3);
            }
        }
        int K = g_kD[c];
        unsigned mask = 0;
#pragma unroll
        for (int w = 0; w < 16; w++)
            mask |= (s[w] <= K) ? (1u << w) : 0u;
        masks[c] = mask;
    }
    __syncthreads();

    // ---- stage E: fused repack + fc (10 x 2048 binary dot) + bf ----
    {
        uint2 mA = *(const uint2*)&masks[2 * L];
        uint2 mB = *(const uint2*)&masks[64 + 2 * L];
        unsigned f0 = mA.x | (mA.y << 16);
        unsigned f1 = mB.x | (mB.y << 16);
        for (int o = W; o < 10; o += 4) {
            int s = __popc(f0 ^ g_wfb[o * 64 + L])
                  + __popc(f1 ^ g_wfb[o * 64 + 32 + L]);
            int tot = __reduce_add_sync(0xffffffffu, s);
            if (L == 0) out[(size_t)b * 10 + o] = (float)(2048 - 2 * tot) + bf[o];
        }
    }
}

extern "C" void kernel_launch(void* const* d_in, const int* in_sizes, int n_in,
                              void* d_out, int out_size)
{
    const float* x   = (const float*)d_in[0];
    const float* w1  = (const float*)d_in[1];
    const float* b1  = (const float*)d_in[2];
    const float* w2  = (const float*)d_in[3];
    const float* b2  = (const float*)d_in[4];
    const float* w3  = (const float*)d_in[5];
    const float* b3  = (const float*)d_in[6];
    const float* w4  = (const float*)d_in[7];
    const float* b4  = (const float*)d_in[8];
    const float* g1  = (const float*)d_in[9];
    const float* be1 = (const float*)d_in[10];
    const float* m1  = (const float*)d_in[11];
    const float* v1  = (const float*)d_in[12];
    const float* g2  = (const float*)d_in[13];
    const float* be2 = (const float*)d_in[14];
    const float* m2  = (const float*)d_in[15];
    const float* v2  = (const float*)d_in[16];
    const float* g3  = (const float*)d_in[17];
    const float* be3 = (const float*)d_in[18];
    const float* m3  = (const float*)d_in[19];
    const float* v3  = (const float*)d_in[20];
    const float* g4  = (const float*)d_in[21];
    const float* be4 = (const float*)d_in[22];
    const float* m4  = (const float*)d_in[23];
    const float* v4  = (const float*)d_in[24];
    const float* wf  = (const float*)d_in[25];
    const float* bf  = (const float*)d_in[26];

    int B = in_sizes[0] / 768;

    prep_kernel<<<22, 256>>>(w1, b1, w2, b2, w3, b3, w4, b4,
                             g1, be1, m1, v1, g2, be2, m2, v2,
                             g3, be3, m3, v3, g4, be4, m4, v4, wf);
    bcnn_kernel<<<B, 128>>>(x, bf, (float*)d_out);
}